// round 1
// baseline (speedup 1.0000x reference)
#include <cuda_runtime.h>
#include <math.h>

// Problem constants
#define BB 2
#define HH 16
#define SS 2048
#define DH 64
#define DM 1024
#define MM (BB*SS)   // 4096 rows

// Scratch (device globals: allocation-free per harness rules)
__device__ float g_q[(size_t)BB*HH*SS*DH];
__device__ float g_k[(size_t)BB*HH*SS*DH];
__device__ float g_v[(size_t)BB*HH*SS*DH];
__device__ float g_ctx[(size_t)MM*DM];

// ---------------------------------------------------------------------------
// SGEMM: C[M,N] = A[M,K] @ W[K,N] + bias, M=4096, N=K=1024 (compile-time)
// Tile 128x128x16, 256 threads, 8x8 per thread (4+4 fragment split for
// conflict-free float4 LDS).
// SPLIT=true: scatter output columns by head into [B,H,S,DH] layout.
// ---------------------------------------------------------------------------
template<bool SPLIT>
__global__ __launch_bounds__(256, 2)
void sgemm_kernel(const float* __restrict__ A, const float* __restrict__ W,
                  const float* __restrict__ bias, float* __restrict__ C)
{
    constexpr int BM = 128, BN = 128, BK = 16;
    __shared__ float As[BK][BM];
    __shared__ float Bs[BK][BN];

    const int tid = threadIdx.x;
    const int tx = tid & 15;       // 0..15 -> N direction
    const int ty = tid >> 4;       // 0..15 -> M direction
    const int bm = blockIdx.y * BM;
    const int bn = blockIdx.x * BN;

    float acc[8][8];
    #pragma unroll
    for (int i = 0; i < 8; i++)
        #pragma unroll
        for (int j = 0; j < 8; j++) acc[i][j] = 0.f;

    for (int k0 = 0; k0 < DM; k0 += BK) {
        // Load A tile (BMxBK) transposed into As, B tile (BKxBN) into Bs.
        #pragma unroll
        for (int i = 0; i < 2; i++) {
            int lin = tid + i * 256;
            int ar = lin >> 2, ac = (lin & 3) << 2;
            float4 av = *(const float4*)(A + (size_t)(bm + ar) * DM + k0 + ac);
            As[ac + 0][ar] = av.x;
            As[ac + 1][ar] = av.y;
            As[ac + 2][ar] = av.z;
            As[ac + 3][ar] = av.w;
            int br = lin >> 5, bc = (lin & 31) << 2;
            *(float4*)&Bs[br][bc] = *(const float4*)(W + (size_t)(k0 + br) * DM + bn + bc);
        }
        __syncthreads();

        #pragma unroll
        for (int kk = 0; kk < BK; kk++) {
            float a[8], b[8];
            *(float4*)&a[0] = *(float4*)&As[kk][ty * 4];
            *(float4*)&a[4] = *(float4*)&As[kk][64 + ty * 4];
            *(float4*)&b[0] = *(float4*)&Bs[kk][tx * 4];
            *(float4*)&b[4] = *(float4*)&Bs[kk][64 + tx * 4];
            #pragma unroll
            for (int i = 0; i < 8; i++)
                #pragma unroll
                for (int j = 0; j < 8; j++)
                    acc[i][j] = fmaf(a[i], b[j], acc[i][j]);
        }
        __syncthreads();
    }

    // Epilogue
    #pragma unroll
    for (int i = 0; i < 8; i++) {
        int mrow = bm + ((i < 4) ? (ty * 4 + i) : (64 + ty * 4 + i - 4));
        #pragma unroll
        for (int j = 0; j < 8; j++) {
            int ncol = bn + ((j < 4) ? (tx * 4 + j) : (64 + tx * 4 + j - 4));
            float v = acc[i][j] + bias[ncol];
            if (!SPLIT) {
                C[(size_t)mrow * DM + ncol] = v;
            } else {
                int h = ncol >> 6, d = ncol & 63;
                int b_ = mrow >> 11, s = mrow & 2047;
                C[((((size_t)b_ * HH + h) * SS + s) * DH) + d] = v;
            }
        }
    }
}

// ---------------------------------------------------------------------------
// Flash attention (non-causal, full softmax), fp32.
// One thread owns one query row: q[64] and o[64] live in registers.
// K/V tiles of 32 rows staged in smem; all compute LDS are warp-broadcast.
// grid: (S/128, B*H), block 128.
// ---------------------------------------------------------------------------
__global__ __launch_bounds__(128)
void flash_kernel(const float* __restrict__ Q, const float* __restrict__ K,
                  const float* __restrict__ V, float* __restrict__ ctx)
{
    constexpr int BM = 128, BN = 32;
    __shared__ float Ks[BN][DH];
    __shared__ float Vs[BN][DH];

    const int tid = threadIdx.x;
    const int bh = blockIdx.y;                 // b*16 + h
    const int q0 = blockIdx.x * BM;

    const float* qp = Q + ((size_t)bh * SS + q0 + tid) * DH;
    float q[DH];
    #pragma unroll
    for (int d = 0; d < DH; d += 4)
        *(float4*)&q[d] = *(const float4*)(qp + d);

    float o[DH];
    #pragma unroll
    for (int d = 0; d < DH; d++) o[d] = 0.f;
    float mx = -1e30f, l = 0.f;

    const float* Kb = K + (size_t)bh * SS * DH;
    const float* Vb = V + (size_t)bh * SS * DH;

    for (int kv = 0; kv < SS; kv += BN) {
        // Stage K/V tile: 32x64 floats each = 512 float4, 4 per thread.
        #pragma unroll
        for (int i = 0; i < 4; i++) {
            int lin = tid + i * 128;
            *(float4*)((float*)Ks + lin * 4) =
                *(const float4*)(Kb + (size_t)kv * DH + lin * 4);
            *(float4*)((float*)Vs + lin * 4) =
                *(const float4*)(Vb + (size_t)kv * DH + lin * 4);
        }
        __syncthreads();

        // scores s[j] = (q . K[j]) * 1/sqrt(64)
        float s[BN];
        #pragma unroll
        for (int j = 0; j < BN; j++) {
            float a = 0.f;
            #pragma unroll
            for (int d = 0; d < DH; d += 4) {
                float4 kk = *(const float4*)&Ks[j][d];
                a = fmaf(q[d + 0], kk.x, a);
                a = fmaf(q[d + 1], kk.y, a);
                a = fmaf(q[d + 2], kk.z, a);
                a = fmaf(q[d + 3], kk.w, a);
            }
            s[j] = a * 0.125f;
        }

        // online softmax update
        float mnew = mx;
        #pragma unroll
        for (int j = 0; j < BN; j++) mnew = fmaxf(mnew, s[j]);
        float alpha = __expf(mx - mnew);
        l *= alpha;
        #pragma unroll
        for (int d = 0; d < DH; d++) o[d] *= alpha;

        #pragma unroll
        for (int j = 0; j < BN; j++) {
            float p = __expf(s[j] - mnew);
            l += p;
            #pragma unroll
            for (int d = 0; d < DH; d += 4) {
                float4 vv = *(const float4*)&Vs[j][d];
                o[d + 0] = fmaf(p, vv.x, o[d + 0]);
                o[d + 1] = fmaf(p, vv.y, o[d + 1]);
                o[d + 2] = fmaf(p, vv.z, o[d + 2]);
                o[d + 3] = fmaf(p, vv.w, o[d + 3]);
            }
        }
        mx = mnew;
        __syncthreads();
    }

    // write ctx in [B, S, H, DH] (i.e. concat-heads row-major [4096, 1024])
    float inv = 1.f / l;
    int b_ = bh >> 4, h = bh & 15;
    float* op = ctx + (((size_t)b_ * SS + q0 + tid) * HH + h) * DH;
    #pragma unroll
    for (int d = 0; d < DH; d += 4) {
        float4 t;
        t.x = o[d + 0] * inv;
        t.y = o[d + 1] * inv;
        t.z = o[d + 2] * inv;
        t.w = o[d + 3] * inv;
        *(float4*)(op + d) = t;
    }
}

// ---------------------------------------------------------------------------
extern "C" void kernel_launch(void* const* d_in, const int* in_sizes, int n_in,
                              void* d_out, int out_size)
{
    const float* x  = (const float*)d_in[0];
    const float* wq = (const float*)d_in[1];
    const float* bq = (const float*)d_in[2];
    const float* wk = (const float*)d_in[3];
    const float* bk = (const float*)d_in[4];
    const float* wv = (const float*)d_in[5];
    const float* bv = (const float*)d_in[6];
    const float* wo = (const float*)d_in[7];
    const float* bo = (const float*)d_in[8];
    float* out = (float*)d_out;

    float *qp, *kp, *vp, *cp;
    cudaGetSymbolAddress((void**)&qp, g_q);
    cudaGetSymbolAddress((void**)&kp, g_k);
    cudaGetSymbolAddress((void**)&vp, g_v);
    cudaGetSymbolAddress((void**)&cp, g_ctx);

    dim3 gg(DM / 128, MM / 128);  // (8, 32)
    sgemm_kernel<true><<<gg, 256>>>(x, wq, bq, qp);
    sgemm_kernel<true><<<gg, 256>>>(x, wk, bk, kp);
    sgemm_kernel<true><<<gg, 256>>>(x, wv, bv, vp);

    flash_kernel<<<dim3(SS / 128, BB * HH), 128>>>(qp, kp, vp, cp);

    sgemm_kernel<false><<<gg, 256>>>(cp, wo, bo, out);
}

// round 4
// speedup vs baseline: 1.2945x; 1.2945x over previous
#include <cuda_runtime.h>
#include <cuda_bf16.h>
#include <math.h>
#include <stdint.h>

// Problem constants
#define BB 2
#define HH 16
#define SS 2048
#define DH 64
#define DM 1024
#define MM (BB*SS)   // 4096 rows

// ---------------------------------------------------------------------------
// Scratch (device globals: allocation-free per harness rules)
// ---------------------------------------------------------------------------
__device__ __align__(256) __nv_bfloat16 g_xh[(size_t)MM*DM];
__device__ __align__(256) __nv_bfloat16 g_xl[(size_t)MM*DM];
__device__ __align__(256) __nv_bfloat16 g_wqh[(size_t)DM*DM];
__device__ __align__(256) __nv_bfloat16 g_wql[(size_t)DM*DM];
__device__ __align__(256) __nv_bfloat16 g_wkh[(size_t)DM*DM];
__device__ __align__(256) __nv_bfloat16 g_wkl[(size_t)DM*DM];
__device__ __align__(256) __nv_bfloat16 g_wvh[(size_t)DM*DM];
__device__ __align__(256) __nv_bfloat16 g_wvl[(size_t)DM*DM];
__device__ __align__(256) __nv_bfloat16 g_woh[(size_t)DM*DM];
__device__ __align__(256) __nv_bfloat16 g_wol[(size_t)DM*DM];
__device__ __align__(256) float g_q[(size_t)BB*HH*SS*DH];
__device__ __align__(256) float g_k[(size_t)BB*HH*SS*DH];
__device__ __align__(256) float g_v[(size_t)BB*HH*SS*DH];
__device__ __align__(256) float g_ctx[(size_t)MM*DM];
__device__ __align__(256) __nv_bfloat16 g_ch[(size_t)MM*DM];
__device__ __align__(256) __nv_bfloat16 g_cl[(size_t)MM*DM];

// ---------------------------------------------------------------------------
// PTX helpers (sm_80+ baseline: mma.sync / ldmatrix / cp.async)
// ---------------------------------------------------------------------------
__device__ __forceinline__ uint32_t smem_u32(const void* p) {
    uint32_t a;
    asm("{ .reg .u64 t; cvta.to.shared.u64 t, %1; cvt.u32.u64 %0, t; }"
        : "=r"(a) : "l"(p));
    return a;
}
__device__ __forceinline__ void cpa16(uint32_t s, const void* g) {
    asm volatile("cp.async.cg.shared.global [%0], [%1], 16;" :: "r"(s), "l"(g));
}
__device__ __forceinline__ void cpa_commit() {
    asm volatile("cp.async.commit_group;" ::: "memory");
}
__device__ __forceinline__ void ldmx4(uint32_t* r, uint32_t addr) {
    asm volatile("ldmatrix.sync.aligned.m8n8.x4.shared.b16 {%0,%1,%2,%3}, [%4];"
                 : "=r"(r[0]), "=r"(r[1]), "=r"(r[2]), "=r"(r[3]) : "r"(addr));
}
__device__ __forceinline__ void mma16816(float* c, const uint32_t* a,
                                         uint32_t b0, uint32_t b1) {
    asm volatile(
        "mma.sync.aligned.m16n8k16.row.col.f32.bf16.bf16.f32 "
        "{%0,%1,%2,%3}, {%4,%5,%6,%7}, {%8,%9}, {%0,%1,%2,%3};"
        : "+f"(c[0]), "+f"(c[1]), "+f"(c[2]), "+f"(c[3])
        : "r"(a[0]), "r"(a[1]), "r"(a[2]), "r"(a[3]), "r"(b0), "r"(b1));
}

// ---------------------------------------------------------------------------
// Split fp32 -> bf16 hi + bf16 lo (elementwise, x and ctx)
// ---------------------------------------------------------------------------
__global__ void split_kernel(const float* __restrict__ in,
                             __nv_bfloat16* __restrict__ hi,
                             __nv_bfloat16* __restrict__ lo, int n)
{
    int i = (blockIdx.x * blockDim.x + threadIdx.x) * 4;
    if (i >= n) return;
    float4 v = *(const float4*)(in + i);
    __nv_bfloat16 h0 = __float2bfloat16(v.x);
    __nv_bfloat16 h1 = __float2bfloat16(v.y);
    __nv_bfloat16 h2 = __float2bfloat16(v.z);
    __nv_bfloat16 h3 = __float2bfloat16(v.w);
    __nv_bfloat16 l0 = __float2bfloat16(v.x - __bfloat162float(h0));
    __nv_bfloat16 l1 = __float2bfloat16(v.y - __bfloat162float(h1));
    __nv_bfloat16 l2 = __float2bfloat16(v.z - __bfloat162float(h2));
    __nv_bfloat16 l3 = __float2bfloat16(v.w - __bfloat162float(h3));
    __nv_bfloat162 ph0; ph0.x = h0; ph0.y = h1;
    __nv_bfloat162 ph1; ph1.x = h2; ph1.y = h3;
    __nv_bfloat162 pl0; pl0.x = l0; pl0.y = l1;
    __nv_bfloat162 pl1; pl1.x = l2; pl1.y = l3;
    ((__nv_bfloat162*)(hi + i))[0] = ph0;
    ((__nv_bfloat162*)(hi + i))[1] = ph1;
    ((__nv_bfloat162*)(lo + i))[0] = pl0;
    ((__nv_bfloat162*)(lo + i))[1] = pl1;
}

// ---------------------------------------------------------------------------
// Transpose + split weights: W[K,N] fp32 -> Th[N,K], Tl[N,K] bf16
// ---------------------------------------------------------------------------
__global__ void wsplit_kernel(const float* __restrict__ W,
                              __nv_bfloat16* __restrict__ Th,
                              __nv_bfloat16* __restrict__ Tl)
{
    __shared__ float t[32][33];
    int n0 = blockIdx.x * 32, k0 = blockIdx.y * 32;
    int tx = threadIdx.x, ty = threadIdx.y; // block (32, 8)
    #pragma unroll
    for (int i = 0; i < 32; i += 8)
        t[ty + i][tx] = W[(size_t)(k0 + ty + i) * DM + n0 + tx];
    __syncthreads();
    #pragma unroll
    for (int i = 0; i < 32; i += 8) {
        float v = t[tx][ty + i];   // = W[k0+tx][n0+ty+i]
        __nv_bfloat16 h = __float2bfloat16(v);
        __nv_bfloat16 l = __float2bfloat16(v - __bfloat162float(h));
        size_t o = (size_t)(n0 + ty + i) * DM + k0 + tx;
        Th[o] = h;
        Tl[o] = l;
    }
}

// ---------------------------------------------------------------------------
// mma.sync bf16 split-GEMM: C[M,N] = (Ah+Al)[M,K] @ (Wh+Wl)^T[N,K] + bias
// 128x128x32 tiles, 256 threads (8 warps, warp tile 32x64), double-buffered
// cp.async, ldmatrix fragments. 3 MMA terms: AhWh + AhWl + AlWh.
// ---------------------------------------------------------------------------
#define GBM 128
#define GBN 128
#define GBK 32
#define LDT 40                 // BK + 8 pad (bf16 elems) -> 80B row stride
#define TILE_B (GBM * LDT * 2) // 10240 B per matrix tile
#define STAGE_B (4 * TILE_B)   // 40960 B per stage
#define GEMM_SMEM (2 * STAGE_B)

// offsets within a stage
#define O_AH 0
#define O_AL TILE_B
#define O_WH (2 * TILE_B)
#define O_WL (3 * TILE_B)

template<bool SPLIT>
__global__ __launch_bounds__(256, 2)
void gemm_bf16_kernel(const __nv_bfloat16* __restrict__ Ah,
                      const __nv_bfloat16* __restrict__ Al,
                      const __nv_bfloat16* __restrict__ Wh,
                      const __nv_bfloat16* __restrict__ Wl,
                      const float* __restrict__ bias,
                      float* __restrict__ C)
{
    extern __shared__ char smem[];
    const uint32_t sbase = smem_u32(smem);
    const int tid = threadIdx.x;
    const int lane = tid & 31;
    const int wid = tid >> 5;
    const int wm = wid & 3;      // 0..3 -> M
    const int wn = wid >> 2;     // 0..1 -> N
    const int bm = blockIdx.y * GBM;
    const int bn = blockIdx.x * GBN;

    float acc[2][8][4];
    #pragma unroll
    for (int i = 0; i < 2; i++)
        #pragma unroll
        for (int j = 0; j < 8; j++)
            #pragma unroll
            for (int e = 0; e < 4; e++) acc[i][j][e] = 0.f;

    // loader mapping: 512 16B-chunks per matrix tile, exactly 2 per thread.
    // Thread covers chunks {2*tid, 2*tid+1}: row = (2*tid)>>2 in [0,127],
    // col = (2*tid)&3 in {0,2}; issues col and col+1.
    const int lrow = tid >> 1;           // (2*tid)>>2
    const int lcol = (tid & 1) * 2;      // (2*tid)&3

    auto load_stage = [&](int buf, int k0) {
        uint32_t sb = sbase + buf * STAGE_B;
        uint32_t so0 = lrow * 80 + lcol * 16;
        uint32_t so1 = so0 + 16;
        size_t ga = (size_t)(bm + lrow) * DM + k0 + lcol * 8;
        size_t gw = (size_t)(bn + lrow) * DM + k0 + lcol * 8;
        cpa16(sb + O_AH + so0, Ah + ga);
        cpa16(sb + O_AH + so1, Ah + ga + 8);
        cpa16(sb + O_AL + so0, Al + ga);
        cpa16(sb + O_AL + so1, Al + ga + 8);
        cpa16(sb + O_WH + so0, Wh + gw);
        cpa16(sb + O_WH + so1, Wh + gw + 8);
        cpa16(sb + O_WL + so0, Wl + gw);
        cpa16(sb + O_WL + so1, Wl + gw + 8);
    };

    // ldmatrix lane mappings
    const int a_row = (lane & 7) + ((lane >> 3) & 1) * 8;
    const int a_kh  = (lane >> 4) * 8;
    const int b_n   = (lane & 7) + ((lane >> 4) & 1) * 8;
    const int b_kh  = ((lane >> 3) & 1) * 8;

    const int T = DM / GBK;  // 32
    load_stage(0, 0);
    cpa_commit();

    for (int t = 0; t < T; t++) {
        if (t + 1 < T) {
            load_stage((t + 1) & 1, (t + 1) * GBK);
            cpa_commit();
            asm volatile("cp.async.wait_group 1;" ::: "memory");
        } else {
            asm volatile("cp.async.wait_group 0;" ::: "memory");
        }
        __syncthreads();

        const uint32_t sb = sbase + (t & 1) * STAGE_B;
        #pragma unroll
        for (int ks = 0; ks < 2; ks++) {
            uint32_t ah[2][4], al[2][4];
            #pragma unroll
            for (int mi = 0; mi < 2; mi++) {
                uint32_t ra = sb + (wm * 32 + mi * 16 + a_row) * 80
                            + (ks * 16 + a_kh) * 2;
                ldmx4(ah[mi], ra + O_AH);
                ldmx4(al[mi], ra + O_AL);
            }
            #pragma unroll
            for (int np = 0; np < 4; np++) {
                uint32_t bh[4], bl[4];
                uint32_t rb = sb + (wn * 64 + np * 16 + b_n) * 80
                            + (ks * 16 + b_kh) * 2;
                ldmx4(bh, rb + O_WH);
                ldmx4(bl, rb + O_WL);
                #pragma unroll
                for (int mi = 0; mi < 2; mi++) {
                    mma16816(acc[mi][np * 2 + 0], ah[mi], bh[0], bh[1]);
                    mma16816(acc[mi][np * 2 + 1], ah[mi], bh[2], bh[3]);
                    mma16816(acc[mi][np * 2 + 0], al[mi], bh[0], bh[1]);
                    mma16816(acc[mi][np * 2 + 1], al[mi], bh[2], bh[3]);
                    mma16816(acc[mi][np * 2 + 0], ah[mi], bl[0], bl[1]);
                    mma16816(acc[mi][np * 2 + 1], ah[mi], bl[2], bl[3]);
                }
            }
        }
        __syncthreads();
    }

    // Epilogue
    #pragma unroll
    for (int mi = 0; mi < 2; mi++) {
        #pragma unroll
        for (int nf = 0; nf < 8; nf++) {
            int gcol = bn + wn * 64 + nf * 8 + (lane & 3) * 2;
            float b0 = __ldg(bias + gcol);
            float b1 = __ldg(bias + gcol + 1);
            #pragma unroll
            for (int half = 0; half < 2; half++) {
                int row = bm + wm * 32 + mi * 16 + (lane >> 2) + half * 8;
                float2 v;
                v.x = acc[mi][nf][half * 2 + 0] + b0;
                v.y = acc[mi][nf][half * 2 + 1] + b1;
                if (SPLIT) {
                    int h = gcol >> 6, d = gcol & 63;
                    int b_ = row >> 11, s = row & 2047;
                    *(float2*)&C[((((size_t)b_ * HH + h) * SS + s) * DH) + d] = v;
                } else {
                    *(float2*)&C[(size_t)row * DM + gcol] = v;
                }
            }
        }
    }
}

// ---------------------------------------------------------------------------
// Flash attention (non-causal), fp32 SIMT. 1 thread = 1 query row.
// ---------------------------------------------------------------------------
__global__ __launch_bounds__(128)
void flash_kernel(const float* __restrict__ Q, const float* __restrict__ K,
                  const float* __restrict__ V, float* __restrict__ ctx)
{
    constexpr int BM = 128, BN = 32;
    __shared__ float Ks[BN][DH];
    __shared__ float Vs[BN][DH];

    const int tid = threadIdx.x;
    const int bh = blockIdx.y;
    const int q0 = blockIdx.x * BM;

    const float* qp = Q + ((size_t)bh * SS + q0 + tid) * DH;
    float q[DH];
    #pragma unroll
    for (int d = 0; d < DH; d += 4)
        *(float4*)&q[d] = *(const float4*)(qp + d);

    float o[DH];
    #pragma unroll
    for (int d = 0; d < DH; d++) o[d] = 0.f;
    float mx = -1e30f, l = 0.f;

    const float* Kb = K + (size_t)bh * SS * DH;
    const float* Vb = V + (size_t)bh * SS * DH;

    for (int kv = 0; kv < SS; kv += BN) {
        #pragma unroll
        for (int i = 0; i < 4; i++) {
            int lin = tid + i * 128;
            *(float4*)((float*)Ks + lin * 4) =
                *(const float4*)(Kb + (size_t)kv * DH + lin * 4);
            *(float4*)((float*)Vs + lin * 4) =
                *(const float4*)(Vb + (size_t)kv * DH + lin * 4);
        }
        __syncthreads();

        float s[BN];
        #pragma unroll
        for (int j = 0; j < BN; j++) {
            float a = 0.f;
            #pragma unroll
            for (int d = 0; d < DH; d += 4) {
                float4 kk = *(const float4*)&Ks[j][d];
                a = fmaf(q[d + 0], kk.x, a);
                a = fmaf(q[d + 1], kk.y, a);
                a = fmaf(q[d + 2], kk.z, a);
                a = fmaf(q[d + 3], kk.w, a);
            }
            s[j] = a * 0.125f;
        }

        float mnew = mx;
        #pragma unroll
        for (int j = 0; j < BN; j++) mnew = fmaxf(mnew, s[j]);
        float alpha = __expf(mx - mnew);
        l *= alpha;
        #pragma unroll
        for (int d = 0; d < DH; d++) o[d] *= alpha;

        #pragma unroll
        for (int j = 0; j < BN; j++) {
            float p = __expf(s[j] - mnew);
            l += p;
            #pragma unroll
            for (int d = 0; d < DH; d += 4) {
                float4 vv = *(const float4*)&Vs[j][d];
                o[d + 0] = fmaf(p, vv.x, o[d + 0]);
                o[d + 1] = fmaf(p, vv.y, o[d + 1]);
                o[d + 2] = fmaf(p, vv.z, o[d + 2]);
                o[d + 3] = fmaf(p, vv.w, o[d + 3]);
            }
        }
        mx = mnew;
        __syncthreads();
    }

    float inv = 1.f / l;
    int b_ = bh >> 4, h = bh & 15;
    float* op = ctx + (((size_t)b_ * SS + q0 + tid) * HH + h) * DH;
    #pragma unroll
    for (int d = 0; d < DH; d += 4) {
        float4 t;
        t.x = o[d + 0] * inv;
        t.y = o[d + 1] * inv;
        t.z = o[d + 2] * inv;
        t.w = o[d + 3] * inv;
        *(float4*)(op + d) = t;
    }
}

// ---------------------------------------------------------------------------
extern "C" void kernel_launch(void* const* d_in, const int* in_sizes, int n_in,
                              void* d_out, int out_size)
{
    const float* x  = (const float*)d_in[0];
    const float* wq = (const float*)d_in[1];
    const float* bq = (const float*)d_in[2];
    const float* wk = (const float*)d_in[3];
    const float* bk = (const float*)d_in[4];
    const float* wv = (const float*)d_in[5];
    const float* bv = (const float*)d_in[6];
    const float* wo = (const float*)d_in[7];
    const float* bo = (const float*)d_in[8];
    float* out = (float*)d_out;

    __nv_bfloat16 *xh, *xl, *wqh, *wql, *wkh, *wkl, *wvh, *wvl, *woh, *wol, *ch, *cl;
    float *qp, *kp, *vp, *cp;
    cudaGetSymbolAddress((void**)&xh, g_xh);
    cudaGetSymbolAddress((void**)&xl, g_xl);
    cudaGetSymbolAddress((void**)&wqh, g_wqh);
    cudaGetSymbolAddress((void**)&wql, g_wql);
    cudaGetSymbolAddress((void**)&wkh, g_wkh);
    cudaGetSymbolAddress((void**)&wkl, g_wkl);
    cudaGetSymbolAddress((void**)&wvh, g_wvh);
    cudaGetSymbolAddress((void**)&wvl, g_wvl);
    cudaGetSymbolAddress((void**)&woh, g_woh);
    cudaGetSymbolAddress((void**)&wol, g_wol);
    cudaGetSymbolAddress((void**)&ch, g_ch);
    cudaGetSymbolAddress((void**)&cl, g_cl);
    cudaGetSymbolAddress((void**)&qp, g_q);
    cudaGetSymbolAddress((void**)&kp, g_k);
    cudaGetSymbolAddress((void**)&vp, g_v);
    cudaGetSymbolAddress((void**)&cp, g_ctx);

    cudaFuncSetAttribute(gemm_bf16_kernel<true>,
                         cudaFuncAttributeMaxDynamicSharedMemorySize, GEMM_SMEM);
    cudaFuncSetAttribute(gemm_bf16_kernel<false>,
                         cudaFuncAttributeMaxDynamicSharedMemorySize, GEMM_SMEM);

    // Split inputs
    const int NX = MM * DM;
    split_kernel<<<NX / (256 * 4), 256>>>(x, xh, xl, NX);
    dim3 wg(DM / 32, DM / 32), wb(32, 8);
    wsplit_kernel<<<wg, wb>>>(wq, wqh, wql);
    wsplit_kernel<<<wg, wb>>>(wk, wkh, wkl);
    wsplit_kernel<<<wg, wb>>>(wv, wvh, wvl);
    wsplit_kernel<<<wg, wb>>>(wo, woh, wol);

    // QKV projections (tensor cores via mma.sync, scattered to [B,H,S,DH])
    dim3 gg(DM / GBN, MM / GBM);  // (8, 32)
    gemm_bf16_kernel<true><<<gg, 256, GEMM_SMEM>>>(xh, xl, wqh, wql, bq, qp);
    gemm_bf16_kernel<true><<<gg, 256, GEMM_SMEM>>>(xh, xl, wkh, wkl, bk, kp);
    gemm_bf16_kernel<true><<<gg, 256, GEMM_SMEM>>>(xh, xl, wvh, wvl, bv, vp);

    // Attention
    flash_kernel<<<dim3(SS / 128, BB * HH), 128>>>(qp, kp, vp, cp);

    // Output projection
    split_kernel<<<NX / (256 * 4), 256>>>(cp, ch, cl, NX);
    gemm_bf16_kernel<false><<<gg, 256, GEMM_SMEM>>>(ch, cl, woh, wol, bo, out);
}

// round 5
// speedup vs baseline: 1.8789x; 1.4514x over previous
#include <cuda_runtime.h>
#include <cuda_bf16.h>
#include <math.h>
#include <stdint.h>

// Problem constants
#define BB 2
#define HH 16
#define SS 2048
#define DH 64
#define DM 1024
#define MM (BB*SS)   // 4096 rows

// ---------------------------------------------------------------------------
// Scratch (device globals: allocation-free per harness rules)
// ---------------------------------------------------------------------------
__device__ __align__(256) __nv_bfloat16 g_xh[(size_t)MM*DM];
__device__ __align__(256) __nv_bfloat16 g_xl[(size_t)MM*DM];
__device__ __align__(256) __nv_bfloat16 g_wqh[(size_t)DM*DM];
__device__ __align__(256) __nv_bfloat16 g_wql[(size_t)DM*DM];
__device__ __align__(256) __nv_bfloat16 g_wkh[(size_t)DM*DM];
__device__ __align__(256) __nv_bfloat16 g_wkl[(size_t)DM*DM];
__device__ __align__(256) __nv_bfloat16 g_wvh[(size_t)DM*DM];
__device__ __align__(256) __nv_bfloat16 g_wvl[(size_t)DM*DM];
__device__ __align__(256) __nv_bfloat16 g_woh[(size_t)DM*DM];
__device__ __align__(256) __nv_bfloat16 g_wol[(size_t)DM*DM];
// Q,K split bf16 in [B,H,S,DH]; V split bf16 transposed [B,H,DH,S]
__device__ __align__(256) __nv_bfloat16 g_qh[(size_t)MM*DM];
__device__ __align__(256) __nv_bfloat16 g_ql[(size_t)MM*DM];
__device__ __align__(256) __nv_bfloat16 g_kh[(size_t)MM*DM];
__device__ __align__(256) __nv_bfloat16 g_kl[(size_t)MM*DM];
__device__ __align__(256) __nv_bfloat16 g_vh[(size_t)MM*DM];
__device__ __align__(256) __nv_bfloat16 g_vl[(size_t)MM*DM];
__device__ __align__(256) float g_ctx[(size_t)MM*DM];
__device__ __align__(256) __nv_bfloat16 g_ch[(size_t)MM*DM];
__device__ __align__(256) __nv_bfloat16 g_cl[(size_t)MM*DM];

// ---------------------------------------------------------------------------
// PTX helpers (sm_80+ baseline: mma.sync / ldmatrix / cp.async)
// ---------------------------------------------------------------------------
__device__ __forceinline__ uint32_t smem_u32(const void* p) {
    uint32_t a;
    asm("{ .reg .u64 t; cvta.to.shared.u64 t, %1; cvt.u32.u64 %0, t; }"
        : "=r"(a) : "l"(p));
    return a;
}
__device__ __forceinline__ void cpa16(uint32_t s, const void* g) {
    asm volatile("cp.async.cg.shared.global [%0], [%1], 16;" :: "r"(s), "l"(g));
}
__device__ __forceinline__ void cpa_commit() {
    asm volatile("cp.async.commit_group;" ::: "memory");
}
__device__ __forceinline__ void ldmx4(uint32_t* r, uint32_t addr) {
    asm volatile("ldmatrix.sync.aligned.m8n8.x4.shared.b16 {%0,%1,%2,%3}, [%4];"
                 : "=r"(r[0]), "=r"(r[1]), "=r"(r[2]), "=r"(r[3]) : "r"(addr));
}
__device__ __forceinline__ void mma16816(float* c, const uint32_t* a,
                                         uint32_t b0, uint32_t b1) {
    asm volatile(
        "mma.sync.aligned.m16n8k16.row.col.f32.bf16.bf16.f32 "
        "{%0,%1,%2,%3}, {%4,%5,%6,%7}, {%8,%9}, {%0,%1,%2,%3};"
        : "+f"(c[0]), "+f"(c[1]), "+f"(c[2]), "+f"(c[3])
        : "r"(a[0]), "r"(a[1]), "r"(a[2]), "r"(a[3]), "r"(b0), "r"(b1));
}
__device__ __forceinline__ uint32_t packbf(float lo, float hi) {
    uint32_t r;
    asm("cvt.rn.bf16x2.f32 %0, %1, %2;" : "=r"(r) : "f"(hi), "f"(lo));
    return r;
}

// ---------------------------------------------------------------------------
// Split fp32 -> bf16 hi + bf16 lo (elementwise, x and ctx)
// ---------------------------------------------------------------------------
__global__ void split_kernel(const float* __restrict__ in,
                             __nv_bfloat16* __restrict__ hi,
                             __nv_bfloat16* __restrict__ lo, int n)
{
    int i = (blockIdx.x * blockDim.x + threadIdx.x) * 4;
    if (i >= n) return;
    float4 v = *(const float4*)(in + i);
    __nv_bfloat16 h0 = __float2bfloat16(v.x);
    __nv_bfloat16 h1 = __float2bfloat16(v.y);
    __nv_bfloat16 h2 = __float2bfloat16(v.z);
    __nv_bfloat16 h3 = __float2bfloat16(v.w);
    __nv_bfloat16 l0 = __float2bfloat16(v.x - __bfloat162float(h0));
    __nv_bfloat16 l1 = __float2bfloat16(v.y - __bfloat162float(h1));
    __nv_bfloat16 l2 = __float2bfloat16(v.z - __bfloat162float(h2));
    __nv_bfloat16 l3 = __float2bfloat16(v.w - __bfloat162float(h3));
    __nv_bfloat162 ph0; ph0.x = h0; ph0.y = h1;
    __nv_bfloat162 ph1; ph1.x = h2; ph1.y = h3;
    __nv_bfloat162 pl0; pl0.x = l0; pl0.y = l1;
    __nv_bfloat162 pl1; pl1.x = l2; pl1.y = l3;
    ((__nv_bfloat162*)(hi + i))[0] = ph0;
    ((__nv_bfloat162*)(hi + i))[1] = ph1;
    ((__nv_bfloat162*)(lo + i))[0] = pl0;
    ((__nv_bfloat162*)(lo + i))[1] = pl1;
}

// ---------------------------------------------------------------------------
// Transpose + split weights: W[K,N] fp32 -> Th[N,K], Tl[N,K] bf16
// ---------------------------------------------------------------------------
__global__ void wsplit_kernel(const float* __restrict__ W,
                              __nv_bfloat16* __restrict__ Th,
                              __nv_bfloat16* __restrict__ Tl)
{
    __shared__ float t[32][33];
    int n0 = blockIdx.x * 32, k0 = blockIdx.y * 32;
    int tx = threadIdx.x, ty = threadIdx.y; // block (32, 8)
    #pragma unroll
    for (int i = 0; i < 32; i += 8)
        t[ty + i][tx] = W[(size_t)(k0 + ty + i) * DM + n0 + tx];
    __syncthreads();
    #pragma unroll
    for (int i = 0; i < 32; i += 8) {
        float v = t[tx][ty + i];   // = W[k0+tx][n0+ty+i]
        __nv_bfloat16 h = __float2bfloat16(v);
        __nv_bfloat16 l = __float2bfloat16(v - __bfloat162float(h));
        size_t o = (size_t)(n0 + ty + i) * DM + k0 + tx;
        Th[o] = h;
        Tl[o] = l;
    }
}

// ---------------------------------------------------------------------------
// mma.sync bf16 split-GEMM: C = (Ah+Al)[M,K] @ (Wh+Wl)^T[N,K] + bias
// MODE 0: fp32 out [M,N].   MODE 1: bf16 hi/lo out in [B,H,S,DH].
// MODE 2: bf16 hi/lo out transposed [B,H,DH,S].
// ---------------------------------------------------------------------------
#define GBM 128
#define GBN 128
#define GBK 32
#define TILE_B (GBM * 40 * 2)  // 80B padded rows, 10240 B per matrix tile
#define STAGE_B (4 * TILE_B)
#define GEMM_SMEM (2 * STAGE_B)
#define O_AH 0
#define O_AL TILE_B
#define O_WH (2 * TILE_B)
#define O_WL (3 * TILE_B)

template<int MODE>
__global__ __launch_bounds__(256, 2)
void gemm_bf16_kernel(const __nv_bfloat16* __restrict__ Ah,
                      const __nv_bfloat16* __restrict__ Al,
                      const __nv_bfloat16* __restrict__ Wh,
                      const __nv_bfloat16* __restrict__ Wl,
                      const float* __restrict__ bias,
                      float* __restrict__ C,
                      __nv_bfloat16* __restrict__ Oh,
                      __nv_bfloat16* __restrict__ Ol)
{
    extern __shared__ char smem[];
    const uint32_t sbase = smem_u32(smem);
    const int tid = threadIdx.x;
    const int lane = tid & 31;
    const int wid = tid >> 5;
    const int wm = wid & 3;
    const int wn = wid >> 2;
    const int bm = blockIdx.y * GBM;
    const int bn = blockIdx.x * GBN;

    float acc[2][8][4];
    #pragma unroll
    for (int i = 0; i < 2; i++)
        #pragma unroll
        for (int j = 0; j < 8; j++)
            #pragma unroll
            for (int e = 0; e < 4; e++) acc[i][j][e] = 0.f;

    const int lrow = tid >> 1;
    const int lcol = (tid & 1) * 2;

    auto load_stage = [&](int buf, int k0) {
        uint32_t sb = sbase + buf * STAGE_B;
        uint32_t so0 = lrow * 80 + lcol * 16;
        uint32_t so1 = so0 + 16;
        size_t ga = (size_t)(bm + lrow) * DM + k0 + lcol * 8;
        size_t gw = (size_t)(bn + lrow) * DM + k0 + lcol * 8;
        cpa16(sb + O_AH + so0, Ah + ga);
        cpa16(sb + O_AH + so1, Ah + ga + 8);
        cpa16(sb + O_AL + so0, Al + ga);
        cpa16(sb + O_AL + so1, Al + ga + 8);
        cpa16(sb + O_WH + so0, Wh + gw);
        cpa16(sb + O_WH + so1, Wh + gw + 8);
        cpa16(sb + O_WL + so0, Wl + gw);
        cpa16(sb + O_WL + so1, Wl + gw + 8);
    };

    const int a_row = (lane & 7) + ((lane >> 3) & 1) * 8;
    const int a_kh  = (lane >> 4) * 8;
    const int b_n   = (lane & 7) + ((lane >> 4) & 1) * 8;
    const int b_kh  = ((lane >> 3) & 1) * 8;

    const int T = DM / GBK;
    load_stage(0, 0);
    cpa_commit();

    for (int t = 0; t < T; t++) {
        if (t + 1 < T) {
            load_stage((t + 1) & 1, (t + 1) * GBK);
            cpa_commit();
            asm volatile("cp.async.wait_group 1;" ::: "memory");
        } else {
            asm volatile("cp.async.wait_group 0;" ::: "memory");
        }
        __syncthreads();

        const uint32_t sb = sbase + (t & 1) * STAGE_B;
        #pragma unroll
        for (int ks = 0; ks < 2; ks++) {
            uint32_t ah[2][4], al[2][4];
            #pragma unroll
            for (int mi = 0; mi < 2; mi++) {
                uint32_t ra = sb + (wm * 32 + mi * 16 + a_row) * 80
                            + (ks * 16 + a_kh) * 2;
                ldmx4(ah[mi], ra + O_AH);
                ldmx4(al[mi], ra + O_AL);
            }
            #pragma unroll
            for (int np = 0; np < 4; np++) {
                uint32_t bh[4], bl[4];
                uint32_t rb = sb + (wn * 64 + np * 16 + b_n) * 80
                            + (ks * 16 + b_kh) * 2;
                ldmx4(bh, rb + O_WH);
                ldmx4(bl, rb + O_WL);
                #pragma unroll
                for (int mi = 0; mi < 2; mi++) {
                    mma16816(acc[mi][np * 2 + 0], ah[mi], bh[0], bh[1]);
                    mma16816(acc[mi][np * 2 + 1], ah[mi], bh[2], bh[3]);
                    mma16816(acc[mi][np * 2 + 0], al[mi], bh[0], bh[1]);
                    mma16816(acc[mi][np * 2 + 1], al[mi], bh[2], bh[3]);
                    mma16816(acc[mi][np * 2 + 0], ah[mi], bl[0], bl[1]);
                    mma16816(acc[mi][np * 2 + 1], ah[mi], bl[2], bl[3]);
                }
            }
        }
        __syncthreads();
    }

    // Epilogue
    #pragma unroll
    for (int mi = 0; mi < 2; mi++) {
        #pragma unroll
        for (int nf = 0; nf < 8; nf++) {
            int gcol = bn + wn * 64 + nf * 8 + (lane & 3) * 2;
            float b0 = __ldg(bias + gcol);
            float b1 = __ldg(bias + gcol + 1);
            #pragma unroll
            for (int half = 0; half < 2; half++) {
                int row = bm + wm * 32 + mi * 16 + (lane >> 2) + half * 8;
                float vx = acc[mi][nf][half * 2 + 0] + b0;
                float vy = acc[mi][nf][half * 2 + 1] + b1;
                if (MODE == 0) {
                    float2 v; v.x = vx; v.y = vy;
                    *(float2*)&C[(size_t)row * DM + gcol] = v;
                } else {
                    int hh = gcol >> 6, d = gcol & 63;
                    int b_ = row >> 11, s = row & 2047;
                    __nv_bfloat16 h0 = __float2bfloat16(vx);
                    __nv_bfloat16 h1 = __float2bfloat16(vy);
                    __nv_bfloat16 l0 = __float2bfloat16(vx - __bfloat162float(h0));
                    __nv_bfloat16 l1 = __float2bfloat16(vy - __bfloat162float(h1));
                    if (MODE == 1) {
                        size_t o = ((((size_t)b_ * HH + hh) * SS + s) * DH) + d;
                        __nv_bfloat162 ph; ph.x = h0; ph.y = h1;
                        __nv_bfloat162 pl; pl.x = l0; pl.y = l1;
                        *(__nv_bfloat162*)&Oh[o] = ph;
                        *(__nv_bfloat162*)&Ol[o] = pl;
                    } else {
                        size_t o = ((((size_t)b_ * HH + hh) * DH + d) * SS) + s;
                        Oh[o] = h0; Oh[o + SS] = h1;
                        Ol[o] = l0; Ol[o + SS] = l1;
                    }
                }
            }
        }
    }
}

// ---------------------------------------------------------------------------
// Tensor-core flash attention, 3-term split bf16 (QK and PV), fp32 softmax.
// Block: 256 threads (8 warps x 16 q-rows = 128 q-rows). 64-key chunks,
// double-buffered cp.async. grid (SS/128, B*H).
// ---------------------------------------------------------------------------
#define FSTR 72                    // padded row: 72 bf16 = 144 B
#define FQ_B (128 * FSTR * 2)      // 18432 B per Q matrix
#define FT_B (64 * FSTR * 2)       // 9216 B per KV matrix tile
#define FO_QH 0
#define FO_QL FQ_B
#define FO_STAGE (2 * FQ_B)        // 36864
#define FSK_H 0
#define FSK_L FT_B
#define FSV_H (2 * FT_B)
#define FSV_L (3 * FT_B)
#define FSTAGE_B (4 * FT_B)        // 36864
#define FLASH_SMEM (FO_STAGE + 2 * FSTAGE_B)  // 110592

__global__ __launch_bounds__(256, 1)
void flash_tc_kernel(const __nv_bfloat16* __restrict__ Qh,
                     const __nv_bfloat16* __restrict__ Ql,
                     const __nv_bfloat16* __restrict__ Kh,
                     const __nv_bfloat16* __restrict__ Kl,
                     const __nv_bfloat16* __restrict__ Vh,
                     const __nv_bfloat16* __restrict__ Vl,
                     float* __restrict__ ctx)
{
    extern __shared__ char smem[];
    const uint32_t sbase = smem_u32(smem);
    const int tid = threadIdx.x;
    const int lane = tid & 31;
    const int wid = tid >> 5;              // 0..7
    const int bh = blockIdx.y;             // b*HH + h
    const int q0 = blockIdx.x * 128;

    const size_t qbase = ((size_t)bh * SS + q0) * DH;
    const size_t kbase = (size_t)bh * SS * DH;
    const size_t vbase = (size_t)bh * DH * SS;

    // ---- load Q tile (128 x 64, hi+lo) ----
    #pragma unroll
    for (int i = 0; i < 4; i++) {
        int c = tid + i * 256;             // 1024 chunks
        int row = c >> 3, col = c & 7;
        uint32_t so = row * 144 + col * 16;
        size_t g = qbase + (size_t)row * DH + col * 8;
        cpa16(sbase + FO_QH + so, Qh + g);
        cpa16(sbase + FO_QL + so, Ql + g);
    }
    cpa_commit();

    auto load_kv = [&](int buf, int kv0) {
        uint32_t sb = sbase + FO_STAGE + buf * FSTAGE_B;
        #pragma unroll
        for (int i = 0; i < 2; i++) {
            int c = tid + i * 256;         // 512 chunks per matrix
            int row = c >> 3, col = c & 7;
            uint32_t so = row * 144 + col * 16;
            size_t gk = kbase + (size_t)(kv0 + row) * DH + col * 8;
            size_t gv = vbase + (size_t)row * SS + kv0 + col * 8;
            cpa16(sb + FSK_H + so, Kh + gk);
            cpa16(sb + FSK_L + so, Kl + gk);
            cpa16(sb + FSV_H + so, Vh + gv);
            cpa16(sb + FSV_L + so, Vl + gv);
        }
    };

    load_kv(0, 0);
    cpa_commit();
    asm volatile("cp.async.wait_group 0;" ::: "memory");
    __syncthreads();

    // ldmatrix lane mappings
    const int a_row = (lane & 7) + ((lane >> 3) & 1) * 8;
    const int a_kh  = (lane >> 4) * 8;
    const int b_n   = (lane & 7) + ((lane >> 4) & 1) * 8;
    const int b_kh  = ((lane >> 3) & 1) * 8;

    // Q fragments (4 k-steps over DH=64)
    uint32_t qfh[4][4], qfl[4][4];
    #pragma unroll
    for (int ks = 0; ks < 4; ks++) {
        uint32_t ra = sbase + (wid * 16 + a_row) * 144 + (ks * 16 + a_kh) * 2;
        ldmx4(qfh[ks], ra + FO_QH);
        ldmx4(qfl[ks], ra + FO_QL);
    }

    float Oa[8][4];
    #pragma unroll
    for (int j = 0; j < 8; j++)
        #pragma unroll
        for (int e = 0; e < 4; e++) Oa[j][e] = 0.f;
    float m0 = -1e30f, m1 = -1e30f, l0 = 0.f, l1 = 0.f;

    const int T = SS / 64;  // 32
    for (int t = 0; t < T; t++) {
        if (t + 1 < T) {
            load_kv((t + 1) & 1, (t + 1) * 64);
            cpa_commit();
            asm volatile("cp.async.wait_group 1;" ::: "memory");
        } else {
            asm volatile("cp.async.wait_group 0;" ::: "memory");
        }
        __syncthreads();

        const uint32_t sb = sbase + FO_STAGE + (t & 1) * FSTAGE_B;

        // ---- S = Q K^T (3-term) ----
        float S[8][4];
        #pragma unroll
        for (int j = 0; j < 8; j++)
            #pragma unroll
            for (int e = 0; e < 4; e++) S[j][e] = 0.f;

        #pragma unroll
        for (int ks = 0; ks < 4; ks++) {
            #pragma unroll
            for (int np = 0; np < 4; np++) {
                uint32_t kh4[4], kl4[4];
                uint32_t rb = sb + (np * 16 + b_n) * 144 + (ks * 16 + b_kh) * 2;
                ldmx4(kh4, rb + FSK_H);
                ldmx4(kl4, rb + FSK_L);
                mma16816(S[np * 2 + 0], qfh[ks], kh4[0], kh4[1]);
                mma16816(S[np * 2 + 1], qfh[ks], kh4[2], kh4[3]);
                mma16816(S[np * 2 + 0], qfh[ks], kl4[0], kl4[1]);
                mma16816(S[np * 2 + 1], qfh[ks], kl4[2], kl4[3]);
                mma16816(S[np * 2 + 0], qfl[ks], kh4[0], kh4[1]);
                mma16816(S[np * 2 + 1], qfl[ks], kh4[2], kh4[3]);
            }
        }

        // ---- online softmax ----
        float rx0 = -1e30f, rx1 = -1e30f;
        #pragma unroll
        for (int j = 0; j < 8; j++) {
            #pragma unroll
            for (int e = 0; e < 4; e++) S[j][e] *= 0.125f;
            rx0 = fmaxf(rx0, fmaxf(S[j][0], S[j][1]));
            rx1 = fmaxf(rx1, fmaxf(S[j][2], S[j][3]));
        }
        rx0 = fmaxf(rx0, __shfl_xor_sync(0xFFFFFFFF, rx0, 1));
        rx0 = fmaxf(rx0, __shfl_xor_sync(0xFFFFFFFF, rx0, 2));
        rx1 = fmaxf(rx1, __shfl_xor_sync(0xFFFFFFFF, rx1, 1));
        rx1 = fmaxf(rx1, __shfl_xor_sync(0xFFFFFFFF, rx1, 2));
        float mn0 = fmaxf(m0, rx0), mn1 = fmaxf(m1, rx1);
        float al0 = __expf(m0 - mn0), al1 = __expf(m1 - mn1);
        l0 *= al0; l1 *= al1;
        #pragma unroll
        for (int j = 0; j < 8; j++) {
            Oa[j][0] *= al0; Oa[j][1] *= al0;
            Oa[j][2] *= al1; Oa[j][3] *= al1;
        }
        #pragma unroll
        for (int j = 0; j < 8; j++) {
            S[j][0] = __expf(S[j][0] - mn0);
            S[j][1] = __expf(S[j][1] - mn0);
            S[j][2] = __expf(S[j][2] - mn1);
            S[j][3] = __expf(S[j][3] - mn1);
            l0 += S[j][0] + S[j][1];
            l1 += S[j][2] + S[j][3];
        }
        m0 = mn0; m1 = mn1;

        // ---- O += P V (3-term) ----
        #pragma unroll
        for (int kc = 0; kc < 4; kc++) {
            uint32_t pah[4], pal[4];
            #pragma unroll
            for (int u = 0; u < 2; u++) {       // two n8 frags -> k halves
                const float* sp = S[kc * 2 + u];
                uint32_t h01 = packbf(sp[0], sp[1]);
                uint32_t h23 = packbf(sp[2], sp[3]);
                float hl0 = __uint_as_float(h01 << 16);
                float hh0 = __uint_as_float(h01 & 0xFFFF0000u);
                float hl1 = __uint_as_float(h23 << 16);
                float hh1 = __uint_as_float(h23 & 0xFFFF0000u);
                pah[u * 2 + 0] = h01;
                pah[u * 2 + 1] = h23;
                pal[u * 2 + 0] = packbf(sp[0] - hl0, sp[1] - hh0);
                pal[u * 2 + 1] = packbf(sp[2] - hl1, sp[3] - hh1);
            }
            // reorder to A-frag: a0=r0 k0-7, a1=r1 k0-7, a2=r0 k8-15, a3=r1 k8-15
            // (u=0 gives k0-7 rows r0,r1; u=1 gives k8-15) -> already matches:
            // pah[0]=r0k0-7, pah[1]=r1k0-7, pah[2]=r0k8-15, pah[3]=r1k8-15. OK.
            #pragma unroll
            for (int np = 0; np < 4; np++) {
                uint32_t vh4[4], vl4[4];
                uint32_t rb = sb + (np * 16 + b_n) * 144 + (kc * 16 + b_kh) * 2;
                ldmx4(vh4, rb + FSV_H);
                ldmx4(vl4, rb + FSV_L);
                mma16816(Oa[np * 2 + 0], pah, vh4[0], vh4[1]);
                mma16816(Oa[np * 2 + 1], pah, vh4[2], vh4[3]);
                mma16816(Oa[np * 2 + 0], pah, vl4[0], vl4[1]);
                mma16816(Oa[np * 2 + 1], pah, vl4[2], vl4[3]);
                mma16816(Oa[np * 2 + 0], pal, vh4[0], vh4[1]);
                mma16816(Oa[np * 2 + 1], pal, vh4[2], vh4[3]);
            }
        }
        __syncthreads();
    }

    // ---- finalize ----
    l0 += __shfl_xor_sync(0xFFFFFFFF, l0, 1);
    l0 += __shfl_xor_sync(0xFFFFFFFF, l0, 2);
    l1 += __shfl_xor_sync(0xFFFFFFFF, l1, 1);
    l1 += __shfl_xor_sync(0xFFFFFFFF, l1, 2);
    float inv0 = 1.f / l0, inv1 = 1.f / l1;

    const int b_ = bh >> 4, h = bh & 15;
    const int r0 = q0 + wid * 16 + (lane >> 2);
    const int col = h * 64 + (lane & 3) * 2;
    #pragma unroll
    for (int nf = 0; nf < 8; nf++) {
        float2 v0, v1;
        v0.x = Oa[nf][0] * inv0; v0.y = Oa[nf][1] * inv0;
        v1.x = Oa[nf][2] * inv1; v1.y = Oa[nf][3] * inv1;
        *(float2*)&ctx[((size_t)b_ * SS + r0) * DM + col + nf * 8] = v0;
        *(float2*)&ctx[((size_t)b_ * SS + r0 + 8) * DM + col + nf * 8] = v1;
    }
}

// ---------------------------------------------------------------------------
extern "C" void kernel_launch(void* const* d_in, const int* in_sizes, int n_in,
                              void* d_out, int out_size)
{
    const float* x  = (const float*)d_in[0];
    const float* wq = (const float*)d_in[1];
    const float* bq = (const float*)d_in[2];
    const float* wk = (const float*)d_in[3];
    const float* bk = (const float*)d_in[4];
    const float* wv = (const float*)d_in[5];
    const float* bv = (const float*)d_in[6];
    const float* wo = (const float*)d_in[7];
    const float* bo = (const float*)d_in[8];
    float* out = (float*)d_out;

    __nv_bfloat16 *xh, *xl, *wqh, *wql, *wkh, *wkl, *wvh, *wvl, *woh, *wol;
    __nv_bfloat16 *qh, *ql, *kh, *kl, *vh, *vl, *ch, *cl;
    float *cp;
    cudaGetSymbolAddress((void**)&xh, g_xh);
    cudaGetSymbolAddress((void**)&xl, g_xl);
    cudaGetSymbolAddress((void**)&wqh, g_wqh);
    cudaGetSymbolAddress((void**)&wql, g_wql);
    cudaGetSymbolAddress((void**)&wkh, g_wkh);
    cudaGetSymbolAddress((void**)&wkl, g_wkl);
    cudaGetSymbolAddress((void**)&wvh, g_wvh);
    cudaGetSymbolAddress((void**)&wvl, g_wvl);
    cudaGetSymbolAddress((void**)&woh, g_woh);
    cudaGetSymbolAddress((void**)&wol, g_wol);
    cudaGetSymbolAddress((void**)&qh, g_qh);
    cudaGetSymbolAddress((void**)&ql, g_ql);
    cudaGetSymbolAddress((void**)&kh, g_kh);
    cudaGetSymbolAddress((void**)&kl, g_kl);
    cudaGetSymbolAddress((void**)&vh, g_vh);
    cudaGetSymbolAddress((void**)&vl, g_vl);
    cudaGetSymbolAddress((void**)&ch, g_ch);
    cudaGetSymbolAddress((void**)&cl, g_cl);
    cudaGetSymbolAddress((void**)&cp, g_ctx);

    cudaFuncSetAttribute(gemm_bf16_kernel<0>,
                         cudaFuncAttributeMaxDynamicSharedMemorySize, GEMM_SMEM);
    cudaFuncSetAttribute(gemm_bf16_kernel<1>,
                         cudaFuncAttributeMaxDynamicSharedMemorySize, GEMM_SMEM);
    cudaFuncSetAttribute(gemm_bf16_kernel<2>,
                         cudaFuncAttributeMaxDynamicSharedMemorySize, GEMM_SMEM);
    cudaFuncSetAttribute(flash_tc_kernel,
                         cudaFuncAttributeMaxDynamicSharedMemorySize, FLASH_SMEM);

    // Split inputs
    const int NX = MM * DM;
    split_kernel<<<NX / (256 * 4), 256>>>(x, xh, xl, NX);
    dim3 wg(DM / 32, DM / 32), wb(32, 8);
    wsplit_kernel<<<wg, wb>>>(wq, wqh, wql);
    wsplit_kernel<<<wg, wb>>>(wk, wkh, wkl);
    wsplit_kernel<<<wg, wb>>>(wv, wvh, wvl);
    wsplit_kernel<<<wg, wb>>>(wo, woh, wol);

    // QKV projections -> split bf16, head layouts
    dim3 gg(DM / GBN, MM / GBM);  // (8, 32)
    gemm_bf16_kernel<1><<<gg, 256, GEMM_SMEM>>>(xh, xl, wqh, wql, bq, nullptr, qh, ql);
    gemm_bf16_kernel<1><<<gg, 256, GEMM_SMEM>>>(xh, xl, wkh, wkl, bk, nullptr, kh, kl);
    gemm_bf16_kernel<2><<<gg, 256, GEMM_SMEM>>>(xh, xl, wvh, wvl, bv, nullptr, vh, vl);

    // Tensor-core attention
    flash_tc_kernel<<<dim3(SS / 128, BB * HH), 256, FLASH_SMEM>>>(
        qh, ql, kh, kl, vh, vl, cp);

    // Output projection
    split_kernel<<<NX / (256 * 4), 256>>>(cp, ch, cl, NX);
    gemm_bf16_kernel<0><<<gg, 256, GEMM_SMEM>>>(ch, cl, woh, wol, bo, out, nullptr, nullptr);
}

// round 6
// speedup vs baseline: 2.9776x; 1.5848x over previous
#include <cuda_runtime.h>
#include <cuda_bf16.h>
#include <math.h>
#include <stdint.h>

// Problem constants
#define BB 2
#define HH 16
#define SS 2048
#define DH 64
#define DM 1024
#define MM (BB*SS)   // 4096 rows

// ---------------------------------------------------------------------------
// Scratch (device globals: allocation-free per harness rules)
// ---------------------------------------------------------------------------
__device__ __align__(256) __nv_bfloat16 g_xh[(size_t)MM*DM];
__device__ __align__(256) __nv_bfloat16 g_xl[(size_t)MM*DM];
__device__ __align__(256) __nv_bfloat16 g_wqh[(size_t)DM*DM];
__device__ __align__(256) __nv_bfloat16 g_wql[(size_t)DM*DM];
__device__ __align__(256) __nv_bfloat16 g_wkh[(size_t)DM*DM];
__device__ __align__(256) __nv_bfloat16 g_wkl[(size_t)DM*DM];
__device__ __align__(256) __nv_bfloat16 g_wvh[(size_t)DM*DM];
__device__ __align__(256) __nv_bfloat16 g_wvl[(size_t)DM*DM];
__device__ __align__(256) __nv_bfloat16 g_woh[(size_t)DM*DM];
__device__ __align__(256) __nv_bfloat16 g_wol[(size_t)DM*DM];
// Q,K split bf16 in [B,H,S,DH]; V split bf16 transposed [B,H,DH,S]
__device__ __align__(256) __nv_bfloat16 g_qh[(size_t)MM*DM];
__device__ __align__(256) __nv_bfloat16 g_ql[(size_t)MM*DM];
__device__ __align__(256) __nv_bfloat16 g_kh[(size_t)MM*DM];
__device__ __align__(256) __nv_bfloat16 g_kl[(size_t)MM*DM];
__device__ __align__(256) __nv_bfloat16 g_vh[(size_t)MM*DM];
__device__ __align__(256) __nv_bfloat16 g_vl[(size_t)MM*DM];
// ctx split bf16 (written directly by flash epilogue)
__device__ __align__(256) __nv_bfloat16 g_ch[(size_t)MM*DM];
__device__ __align__(256) __nv_bfloat16 g_cl[(size_t)MM*DM];

// ---------------------------------------------------------------------------
// PTX helpers (sm_80+ baseline: mma.sync / ldmatrix / cp.async)
// ---------------------------------------------------------------------------
__device__ __forceinline__ uint32_t smem_u32(const void* p) {
    uint32_t a;
    asm("{ .reg .u64 t; cvta.to.shared.u64 t, %1; cvt.u32.u64 %0, t; }"
        : "=r"(a) : "l"(p));
    return a;
}
__device__ __forceinline__ void cpa16(uint32_t s, const void* g) {
    asm volatile("cp.async.cg.shared.global [%0], [%1], 16;" :: "r"(s), "l"(g));
}
__device__ __forceinline__ void cpa_commit() {
    asm volatile("cp.async.commit_group;" ::: "memory");
}
__device__ __forceinline__ void ldmx4(uint32_t* r, uint32_t addr) {
    asm volatile("ldmatrix.sync.aligned.m8n8.x4.shared.b16 {%0,%1,%2,%3}, [%4];"
                 : "=r"(r[0]), "=r"(r[1]), "=r"(r[2]), "=r"(r[3]) : "r"(addr));
}
__device__ __forceinline__ void mma16816(float* c, const uint32_t* a,
                                         uint32_t b0, uint32_t b1) {
    asm volatile(
        "mma.sync.aligned.m16n8k16.row.col.f32.bf16.bf16.f32 "
        "{%0,%1,%2,%3}, {%4,%5,%6,%7}, {%8,%9}, {%0,%1,%2,%3};"
        : "+f"(c[0]), "+f"(c[1]), "+f"(c[2]), "+f"(c[3])
        : "r"(a[0]), "r"(a[1]), "r"(a[2]), "r"(a[3]), "r"(b0), "r"(b1));
}
__device__ __forceinline__ uint32_t packbf(float lo, float hi) {
    uint32_t r;
    asm("cvt.rn.bf16x2.f32 %0, %1, %2;" : "=r"(r) : "f"(hi), "f"(lo));
    return r;
}

// ---------------------------------------------------------------------------
// Split fp32 -> bf16 hi + bf16 lo (elementwise, x)
// ---------------------------------------------------------------------------
__global__ void split_kernel(const float* __restrict__ in,
                             __nv_bfloat16* __restrict__ hi,
                             __nv_bfloat16* __restrict__ lo, int n)
{
    int i = (blockIdx.x * blockDim.x + threadIdx.x) * 4;
    if (i >= n) return;
    float4 v = *(const float4*)(in + i);
    __nv_bfloat16 h0 = __float2bfloat16(v.x);
    __nv_bfloat16 h1 = __float2bfloat16(v.y);
    __nv_bfloat16 h2 = __float2bfloat16(v.z);
    __nv_bfloat16 h3 = __float2bfloat16(v.w);
    __nv_bfloat16 l0 = __float2bfloat16(v.x - __bfloat162float(h0));
    __nv_bfloat16 l1 = __float2bfloat16(v.y - __bfloat162float(h1));
    __nv_bfloat16 l2 = __float2bfloat16(v.z - __bfloat162float(h2));
    __nv_bfloat16 l3 = __float2bfloat16(v.w - __bfloat162float(h3));
    __nv_bfloat162 ph0; ph0.x = h0; ph0.y = h1;
    __nv_bfloat162 ph1; ph1.x = h2; ph1.y = h3;
    __nv_bfloat162 pl0; pl0.x = l0; pl0.y = l1;
    __nv_bfloat162 pl1; pl1.x = l2; pl1.y = l3;
    ((__nv_bfloat162*)(hi + i))[0] = ph0;
    ((__nv_bfloat162*)(hi + i))[1] = ph1;
    ((__nv_bfloat162*)(lo + i))[0] = pl0;
    ((__nv_bfloat162*)(lo + i))[1] = pl1;
}

// ---------------------------------------------------------------------------
// Transpose + split weights: W[K,N] fp32 -> Th[N,K], Tl[N,K] bf16
// ---------------------------------------------------------------------------
__global__ void wsplit_kernel(const float* __restrict__ W,
                              __nv_bfloat16* __restrict__ Th,
                              __nv_bfloat16* __restrict__ Tl)
{
    __shared__ float t[32][33];
    int n0 = blockIdx.x * 32, k0 = blockIdx.y * 32;
    int tx = threadIdx.x, ty = threadIdx.y; // block (32, 8)
    #pragma unroll
    for (int i = 0; i < 32; i += 8)
        t[ty + i][tx] = W[(size_t)(k0 + ty + i) * DM + n0 + tx];
    __syncthreads();
    #pragma unroll
    for (int i = 0; i < 32; i += 8) {
        float v = t[tx][ty + i];   // = W[k0+tx][n0+ty+i]
        __nv_bfloat16 h = __float2bfloat16(v);
        __nv_bfloat16 l = __float2bfloat16(v - __bfloat162float(h));
        size_t o = (size_t)(n0 + ty + i) * DM + k0 + tx;
        Th[o] = h;
        Tl[o] = l;
    }
}

// ---------------------------------------------------------------------------
// mma.sync bf16 split-GEMM: C = (Ah+Al)[M,K] @ (Wh+Wl)^T[N,K] + bias
// MODE 0: fp32 out [M,N].   MODE 1: bf16 hi/lo out in [B,H,S,DH].
// MODE 2: bf16 hi/lo out transposed [B,H,DH,S].
// ---------------------------------------------------------------------------
#define GBM 128
#define GBN 128
#define GBK 32
#define TILE_B (GBM * 40 * 2)  // 80B padded rows, 10240 B per matrix tile
#define STAGE_B (4 * TILE_B)
#define GEMM_SMEM (2 * STAGE_B)
#define O_AH 0
#define O_AL TILE_B
#define O_WH (2 * TILE_B)
#define O_WL (3 * TILE_B)

template<int MODE>
__global__ __launch_bounds__(256, 2)
void gemm_bf16_kernel(const __nv_bfloat16* __restrict__ Ah,
                      const __nv_bfloat16* __restrict__ Al,
                      const __nv_bfloat16* __restrict__ Wh,
                      const __nv_bfloat16* __restrict__ Wl,
                      const float* __restrict__ bias,
                      float* __restrict__ C,
                      __nv_bfloat16* __restrict__ Oh,
                      __nv_bfloat16* __restrict__ Ol)
{
    extern __shared__ char smem[];
    const uint32_t sbase = smem_u32(smem);
    const int tid = threadIdx.x;
    const int lane = tid & 31;
    const int wid = tid >> 5;
    const int wm = wid & 3;
    const int wn = wid >> 2;
    const int bm = blockIdx.y * GBM;
    const int bn = blockIdx.x * GBN;

    float acc[2][8][4];
    #pragma unroll
    for (int i = 0; i < 2; i++)
        #pragma unroll
        for (int j = 0; j < 8; j++)
            #pragma unroll
            for (int e = 0; e < 4; e++) acc[i][j][e] = 0.f;

    const int lrow = tid >> 1;
    const int lcol = (tid & 1) * 2;

    auto load_stage = [&](int buf, int k0) {
        uint32_t sb = sbase + buf * STAGE_B;
        uint32_t so0 = lrow * 80 + lcol * 16;
        uint32_t so1 = so0 + 16;
        size_t ga = (size_t)(bm + lrow) * DM + k0 + lcol * 8;
        size_t gw = (size_t)(bn + lrow) * DM + k0 + lcol * 8;
        cpa16(sb + O_AH + so0, Ah + ga);
        cpa16(sb + O_AH + so1, Ah + ga + 8);
        cpa16(sb + O_AL + so0, Al + ga);
        cpa16(sb + O_AL + so1, Al + ga + 8);
        cpa16(sb + O_WH + so0, Wh + gw);
        cpa16(sb + O_WH + so1, Wh + gw + 8);
        cpa16(sb + O_WL + so0, Wl + gw);
        cpa16(sb + O_WL + so1, Wl + gw + 8);
    };

    const int a_row = (lane & 7) + ((lane >> 3) & 1) * 8;
    const int a_kh  = (lane >> 4) * 8;
    const int b_n   = (lane & 7) + ((lane >> 4) & 1) * 8;
    const int b_kh  = ((lane >> 3) & 1) * 8;

    const int T = DM / GBK;
    load_stage(0, 0);
    cpa_commit();

    for (int t = 0; t < T; t++) {
        if (t + 1 < T) {
            load_stage((t + 1) & 1, (t + 1) * GBK);
            cpa_commit();
            asm volatile("cp.async.wait_group 1;" ::: "memory");
        } else {
            asm volatile("cp.async.wait_group 0;" ::: "memory");
        }
        __syncthreads();

        const uint32_t sb = sbase + (t & 1) * STAGE_B;
        #pragma unroll
        for (int ks = 0; ks < 2; ks++) {
            uint32_t ah[2][4], al[2][4];
            #pragma unroll
            for (int mi = 0; mi < 2; mi++) {
                uint32_t ra = sb + (wm * 32 + mi * 16 + a_row) * 80
                            + (ks * 16 + a_kh) * 2;
                ldmx4(ah[mi], ra + O_AH);
                ldmx4(al[mi], ra + O_AL);
            }
            #pragma unroll
            for (int np = 0; np < 4; np++) {
                uint32_t bh[4], bl[4];
                uint32_t rb = sb + (wn * 64 + np * 16 + b_n) * 80
                            + (ks * 16 + b_kh) * 2;
                ldmx4(bh, rb + O_WH);
                ldmx4(bl, rb + O_WL);
                #pragma unroll
                for (int mi = 0; mi < 2; mi++) {
                    mma16816(acc[mi][np * 2 + 0], ah[mi], bh[0], bh[1]);
                    mma16816(acc[mi][np * 2 + 1], ah[mi], bh[2], bh[3]);
                    mma16816(acc[mi][np * 2 + 0], al[mi], bh[0], bh[1]);
                    mma16816(acc[mi][np * 2 + 1], al[mi], bh[2], bh[3]);
                    mma16816(acc[mi][np * 2 + 0], ah[mi], bl[0], bl[1]);
                    mma16816(acc[mi][np * 2 + 1], ah[mi], bl[2], bl[3]);
                }
            }
        }
        __syncthreads();
    }

    // Epilogue
    #pragma unroll
    for (int mi = 0; mi < 2; mi++) {
        #pragma unroll
        for (int nf = 0; nf < 8; nf++) {
            int gcol = bn + wn * 64 + nf * 8 + (lane & 3) * 2;
            float b0 = __ldg(bias + gcol);
            float b1 = __ldg(bias + gcol + 1);
            #pragma unroll
            for (int half = 0; half < 2; half++) {
                int row = bm + wm * 32 + mi * 16 + (lane >> 2) + half * 8;
                float vx = acc[mi][nf][half * 2 + 0] + b0;
                float vy = acc[mi][nf][half * 2 + 1] + b1;
                if (MODE == 0) {
                    float2 v; v.x = vx; v.y = vy;
                    *(float2*)&C[(size_t)row * DM + gcol] = v;
                } else {
                    int hh = gcol >> 6, d = gcol & 63;
                    int b_ = row >> 11, s = row & 2047;
                    __nv_bfloat16 h0 = __float2bfloat16(vx);
                    __nv_bfloat16 h1 = __float2bfloat16(vy);
                    __nv_bfloat16 l0 = __float2bfloat16(vx - __bfloat162float(h0));
                    __nv_bfloat16 l1 = __float2bfloat16(vy - __bfloat162float(h1));
                    if (MODE == 1) {
                        size_t o = ((((size_t)b_ * HH + hh) * SS + s) * DH) + d;
                        __nv_bfloat162 ph; ph.x = h0; ph.y = h1;
                        __nv_bfloat162 pl; pl.x = l0; pl.y = l1;
                        *(__nv_bfloat162*)&Oh[o] = ph;
                        *(__nv_bfloat162*)&Ol[o] = pl;
                    } else {
                        size_t o = ((((size_t)b_ * HH + hh) * DH + d) * SS) + s;
                        Oh[o] = h0; Oh[o + SS] = h1;
                        Ol[o] = l0; Ol[o + SS] = l1;
                    }
                }
            }
        }
    }
}

// ---------------------------------------------------------------------------
// Tensor-core flash attention, 3-term split bf16 (QK and PV), fp32 softmax.
// 256 threads (8 warps x 16 q-rows), 64-key double-buffered chunks.
// 2 CTAs/SM: Q fragments re-loaded from smem each chunk to keep regs <= 128,
// so one CTA's softmax overlaps the other's MMAs.
// Epilogue writes ctx directly as bf16 hi/lo (row-major [MM, DM]).
// ---------------------------------------------------------------------------
#define FSTR 72                    // padded row: 72 bf16 = 144 B
#define FQ_B (128 * FSTR * 2)      // 18432 B per Q matrix
#define FT_B (64 * FSTR * 2)       // 9216 B per KV matrix tile
#define FO_QH 0
#define FO_QL FQ_B
#define FO_STAGE (2 * FQ_B)        // 36864
#define FSK_H 0
#define FSK_L FT_B
#define FSV_H (2 * FT_B)
#define FSV_L (3 * FT_B)
#define FSTAGE_B (4 * FT_B)        // 36864
#define FLASH_SMEM (FO_STAGE + 2 * FSTAGE_B)  // 110592

__global__ __launch_bounds__(256, 2)
void flash_tc_kernel(const __nv_bfloat16* __restrict__ Qh,
                     const __nv_bfloat16* __restrict__ Ql,
                     const __nv_bfloat16* __restrict__ Kh,
                     const __nv_bfloat16* __restrict__ Kl,
                     const __nv_bfloat16* __restrict__ Vh,
                     const __nv_bfloat16* __restrict__ Vl,
                     __nv_bfloat16* __restrict__ Ch,
                     __nv_bfloat16* __restrict__ Cl)
{
    extern __shared__ char smem[];
    const uint32_t sbase = smem_u32(smem);
    const int tid = threadIdx.x;
    const int lane = tid & 31;
    const int wid = tid >> 5;              // 0..7
    const int bh = blockIdx.y;             // b*HH + h
    const int q0 = blockIdx.x * 128;

    const size_t qbase = ((size_t)bh * SS + q0) * DH;
    const size_t kbase = (size_t)bh * SS * DH;
    const size_t vbase = (size_t)bh * DH * SS;

    // ---- load Q tile (128 x 64, hi+lo) ----
    #pragma unroll
    for (int i = 0; i < 4; i++) {
        int c = tid + i * 256;             // 1024 chunks
        int row = c >> 3, col = c & 7;
        uint32_t so = row * 144 + col * 16;
        size_t g = qbase + (size_t)row * DH + col * 8;
        cpa16(sbase + FO_QH + so, Qh + g);
        cpa16(sbase + FO_QL + so, Ql + g);
    }
    cpa_commit();

    auto load_kv = [&](int buf, int kv0) {
        uint32_t sb = sbase + FO_STAGE + buf * FSTAGE_B;
        #pragma unroll
        for (int i = 0; i < 2; i++) {
            int c = tid + i * 256;         // 512 chunks per matrix
            int row = c >> 3, col = c & 7;
            uint32_t so = row * 144 + col * 16;
            size_t gk = kbase + (size_t)(kv0 + row) * DH + col * 8;
            size_t gv = vbase + (size_t)row * SS + kv0 + col * 8;
            cpa16(sb + FSK_H + so, Kh + gk);
            cpa16(sb + FSK_L + so, Kl + gk);
            cpa16(sb + FSV_H + so, Vh + gv);
            cpa16(sb + FSV_L + so, Vl + gv);
        }
    };

    load_kv(0, 0);
    cpa_commit();
    asm volatile("cp.async.wait_group 0;" ::: "memory");
    __syncthreads();

    // ldmatrix lane mappings
    const int a_row = (lane & 7) + ((lane >> 3) & 1) * 8;
    const int a_kh  = (lane >> 4) * 8;
    const int b_n   = (lane & 7) + ((lane >> 4) & 1) * 8;
    const int b_kh  = ((lane >> 3) & 1) * 8;

    float Oa[8][4];
    #pragma unroll
    for (int j = 0; j < 8; j++)
        #pragma unroll
        for (int e = 0; e < 4; e++) Oa[j][e] = 0.f;
    float m0 = -1e30f, m1 = -1e30f, l0 = 0.f, l1 = 0.f;

    const int T = SS / 64;  // 32
    for (int t = 0; t < T; t++) {
        if (t + 1 < T) {
            load_kv((t + 1) & 1, (t + 1) * 64);
            cpa_commit();
            asm volatile("cp.async.wait_group 1;" ::: "memory");
        } else {
            asm volatile("cp.async.wait_group 0;" ::: "memory");
        }
        __syncthreads();

        const uint32_t sb = sbase + FO_STAGE + (t & 1) * FSTAGE_B;

        // ---- S = Q K^T (3-term); Q frags re-loaded from smem per ks ----
        float S[8][4];
        #pragma unroll
        for (int j = 0; j < 8; j++)
            #pragma unroll
            for (int e = 0; e < 4; e++) S[j][e] = 0.f;

        #pragma unroll
        for (int ks = 0; ks < 4; ks++) {
            uint32_t qh4[4], ql4[4];
            uint32_t ra = sbase + (wid * 16 + a_row) * 144 + (ks * 16 + a_kh) * 2;
            ldmx4(qh4, ra + FO_QH);
            ldmx4(ql4, ra + FO_QL);
            #pragma unroll
            for (int np = 0; np < 4; np++) {
                uint32_t kh4[4], kl4[4];
                uint32_t rb = sb + (np * 16 + b_n) * 144 + (ks * 16 + b_kh) * 2;
                ldmx4(kh4, rb + FSK_H);
                ldmx4(kl4, rb + FSK_L);
                mma16816(S[np * 2 + 0], qh4, kh4[0], kh4[1]);
                mma16816(S[np * 2 + 1], qh4, kh4[2], kh4[3]);
                mma16816(S[np * 2 + 0], qh4, kl4[0], kl4[1]);
                mma16816(S[np * 2 + 1], qh4, kl4[2], kl4[3]);
                mma16816(S[np * 2 + 0], ql4, kh4[0], kh4[1]);
                mma16816(S[np * 2 + 1], ql4, kh4[2], kh4[3]);
            }
        }

        // ---- online softmax ----
        float rx0 = -1e30f, rx1 = -1e30f;
        #pragma unroll
        for (int j = 0; j < 8; j++) {
            #pragma unroll
            for (int e = 0; e < 4; e++) S[j][e] *= 0.125f;
            rx0 = fmaxf(rx0, fmaxf(S[j][0], S[j][1]));
            rx1 = fmaxf(rx1, fmaxf(S[j][2], S[j][3]));
        }
        rx0 = fmaxf(rx0, __shfl_xor_sync(0xFFFFFFFF, rx0, 1));
        rx0 = fmaxf(rx0, __shfl_xor_sync(0xFFFFFFFF, rx0, 2));
        rx1 = fmaxf(rx1, __shfl_xor_sync(0xFFFFFFFF, rx1, 1));
        rx1 = fmaxf(rx1, __shfl_xor_sync(0xFFFFFFFF, rx1, 2));
        float mn0 = fmaxf(m0, rx0), mn1 = fmaxf(m1, rx1);
        float al0 = __expf(m0 - mn0), al1 = __expf(m1 - mn1);
        l0 *= al0; l1 *= al1;
        #pragma unroll
        for (int j = 0; j < 8; j++) {
            Oa[j][0] *= al0; Oa[j][1] *= al0;
            Oa[j][2] *= al1; Oa[j][3] *= al1;
        }
        #pragma unroll
        for (int j = 0; j < 8; j++) {
            S[j][0] = __expf(S[j][0] - mn0);
            S[j][1] = __expf(S[j][1] - mn0);
            S[j][2] = __expf(S[j][2] - mn1);
            S[j][3] = __expf(S[j][3] - mn1);
            l0 += S[j][0] + S[j][1];
            l1 += S[j][2] + S[j][3];
        }
        m0 = mn0; m1 = mn1;

        // ---- O += P V (3-term) ----
        #pragma unroll
        for (int kc = 0; kc < 4; kc++) {
            uint32_t pah[4], pal[4];
            #pragma unroll
            for (int u = 0; u < 2; u++) {
                const float* sp = S[kc * 2 + u];
                uint32_t h01 = packbf(sp[0], sp[1]);
                uint32_t h23 = packbf(sp[2], sp[3]);
                float hl0 = __uint_as_float(h01 << 16);
                float hh0 = __uint_as_float(h01 & 0xFFFF0000u);
                float hl1 = __uint_as_float(h23 << 16);
                float hh1 = __uint_as_float(h23 & 0xFFFF0000u);
                pah[u * 2 + 0] = h01;
                pah[u * 2 + 1] = h23;
                pal[u * 2 + 0] = packbf(sp[0] - hl0, sp[1] - hh0);
                pal[u * 2 + 1] = packbf(sp[2] - hl1, sp[3] - hh1);
            }
            #pragma unroll
            for (int np = 0; np < 4; np++) {
                uint32_t vh4[4], vl4[4];
                uint32_t rb = sb + (np * 16 + b_n) * 144 + (kc * 16 + b_kh) * 2;
                ldmx4(vh4, rb + FSV_H);
                ldmx4(vl4, rb + FSV_L);
                mma16816(Oa[np * 2 + 0], pah, vh4[0], vh4[1]);
                mma16816(Oa[np * 2 + 1], pah, vh4[2], vh4[3]);
                mma16816(Oa[np * 2 + 0], pah, vl4[0], vl4[1]);
                mma16816(Oa[np * 2 + 1], pah, vl4[2], vl4[3]);
                mma16816(Oa[np * 2 + 0], pal, vh4[0], vh4[1]);
                mma16816(Oa[np * 2 + 1], pal, vh4[2], vh4[3]);
            }
        }
        __syncthreads();
    }

    // ---- finalize: write ctx as bf16 hi/lo, row-major [MM, DM] ----
    l0 += __shfl_xor_sync(0xFFFFFFFF, l0, 1);
    l0 += __shfl_xor_sync(0xFFFFFFFF, l0, 2);
    l1 += __shfl_xor_sync(0xFFFFFFFF, l1, 1);
    l1 += __shfl_xor_sync(0xFFFFFFFF, l1, 2);
    float inv0 = 1.f / l0, inv1 = 1.f / l1;

    const int b_ = bh >> 4, h = bh & 15;
    const int r0 = q0 + wid * 16 + (lane >> 2);
    const int col = h * 64 + (lane & 3) * 2;
    #pragma unroll
    for (int nf = 0; nf < 8; nf++) {
        #pragma unroll
        for (int half = 0; half < 2; half++) {
            float inv = half ? inv1 : inv0;
            float vx = Oa[nf][half * 2 + 0] * inv;
            float vy = Oa[nf][half * 2 + 1] * inv;
            __nv_bfloat16 h0 = __float2bfloat16(vx);
            __nv_bfloat16 h1 = __float2bfloat16(vy);
            __nv_bfloat16 lo0 = __float2bfloat16(vx - __bfloat162float(h0));
            __nv_bfloat16 lo1 = __float2bfloat16(vy - __bfloat162float(h1));
            size_t o = ((size_t)b_ * SS + r0 + half * 8) * DM + col + nf * 8;
            __nv_bfloat162 ph; ph.x = h0; ph.y = h1;
            __nv_bfloat162 pl; pl.x = lo0; pl.y = lo1;
            *(__nv_bfloat162*)&Ch[o] = ph;
            *(__nv_bfloat162*)&Cl[o] = pl;
        }
    }
}

// ---------------------------------------------------------------------------
extern "C" void kernel_launch(void* const* d_in, const int* in_sizes, int n_in,
                              void* d_out, int out_size)
{
    const float* x  = (const float*)d_in[0];
    const float* wq = (const float*)d_in[1];
    const float* bq = (const float*)d_in[2];
    const float* wk = (const float*)d_in[3];
    const float* bk = (const float*)d_in[4];
    const float* wv = (const float*)d_in[5];
    const float* bv = (const float*)d_in[6];
    const float* wo = (const float*)d_in[7];
    const float* bo = (const float*)d_in[8];
    float* out = (float*)d_out;

    __nv_bfloat16 *xh, *xl, *wqh, *wql, *wkh, *wkl, *wvh, *wvl, *woh, *wol;
    __nv_bfloat16 *qh, *ql, *kh, *kl, *vh, *vl, *ch, *cl;
    cudaGetSymbolAddress((void**)&xh, g_xh);
    cudaGetSymbolAddress((void**)&xl, g_xl);
    cudaGetSymbolAddress((void**)&wqh, g_wqh);
    cudaGetSymbolAddress((void**)&wql, g_wql);
    cudaGetSymbolAddress((void**)&wkh, g_wkh);
    cudaGetSymbolAddress((void**)&wkl, g_wkl);
    cudaGetSymbolAddress((void**)&wvh, g_wvh);
    cudaGetSymbolAddress((void**)&wvl, g_wvl);
    cudaGetSymbolAddress((void**)&woh, g_woh);
    cudaGetSymbolAddress((void**)&wol, g_wol);
    cudaGetSymbolAddress((void**)&qh, g_qh);
    cudaGetSymbolAddress((void**)&ql, g_ql);
    cudaGetSymbolAddress((void**)&kh, g_kh);
    cudaGetSymbolAddress((void**)&kl, g_kl);
    cudaGetSymbolAddress((void**)&vh, g_vh);
    cudaGetSymbolAddress((void**)&vl, g_vl);
    cudaGetSymbolAddress((void**)&ch, g_ch);
    cudaGetSymbolAddress((void**)&cl, g_cl);

    cudaFuncSetAttribute(gemm_bf16_kernel<0>,
                         cudaFuncAttributeMaxDynamicSharedMemorySize, GEMM_SMEM);
    cudaFuncSetAttribute(gemm_bf16_kernel<1>,
                         cudaFuncAttributeMaxDynamicSharedMemorySize, GEMM_SMEM);
    cudaFuncSetAttribute(gemm_bf16_kernel<2>,
                         cudaFuncAttributeMaxDynamicSharedMemorySize, GEMM_SMEM);
    cudaFuncSetAttribute(flash_tc_kernel,
                         cudaFuncAttributeMaxDynamicSharedMemorySize, FLASH_SMEM);

    // Split inputs
    const int NX = MM * DM;
    split_kernel<<<NX / (256 * 4), 256>>>(x, xh, xl, NX);
    dim3 wg(DM / 32, DM / 32), wb(32, 8);
    wsplit_kernel<<<wg, wb>>>(wq, wqh, wql);
    wsplit_kernel<<<wg, wb>>>(wk, wkh, wkl);
    wsplit_kernel<<<wg, wb>>>(wv, wvh, wvl);
    wsplit_kernel<<<wg, wb>>>(wo, woh, wol);

    // QKV projections -> split bf16, head layouts
    dim3 gg(DM / GBN, MM / GBM);  // (8, 32)
    gemm_bf16_kernel<1><<<gg, 256, GEMM_SMEM>>>(xh, xl, wqh, wql, bq, nullptr, qh, ql);
    gemm_bf16_kernel<1><<<gg, 256, GEMM_SMEM>>>(xh, xl, wkh, wkl, bk, nullptr, kh, kl);
    gemm_bf16_kernel<2><<<gg, 256, GEMM_SMEM>>>(xh, xl, wvh, wvl, bv, nullptr, vh, vl);

    // Tensor-core attention (writes ctx split bf16 directly)
    flash_tc_kernel<<<dim3(SS / 128, BB * HH), 256, FLASH_SMEM>>>(
        qh, ql, kh, kl, vh, vl, ch, cl);

    // Output projection
    gemm_bf16_kernel<0><<<gg, 256, GEMM_SMEM>>>(ch, cl, woh, wol, bo, out, nullptr, nullptr);
}